// round 15
// baseline (speedup 1.0000x reference)
#include <cuda_runtime.h>
#include <math.h>

#define NU 10000
#define NP 50000
#define SL 100
#define D  128
#define NHD 8
#define HD 16
#define NN 60001
#define BB 1024
#define NNZG 1920000
#define NNZH 1600000
#define MROWS (BB*SL)
#define NGROWS 60000

// ---------------- scratch (static device globals; no allocs) ----------------
__device__ float g_nodes[NN*D];       // node buffer A
__device__ float g_acc[NN*D];
__device__ float g_tmp[(NN-1)*D];     // node buffer B
__device__ float g_gx[NP*D];
__device__ float g_gacc[NP*D];
__device__ float g_gt[NP*D];
__device__ float g_seq[MROWS*D];      // seq_e / seq_h
__device__ float g_t1[MROWS*D];       // geo out / tot / nh1
__device__ float g_t2[MROWS*D];       // outproj out / glu1 out
__device__ float g_qkv[MROWS*3*D];    // qkv
__device__ float g_o[MROWS*D];        // attn out
__device__ float g_users[BB*D];       // per-layer user embeddings / hs@glu2
__device__ float g_hs[BB*D];
// CSR scratch
__device__ int   g_Gptr[NGROWS+1];
__device__ int   g_Gcur[NGROWS+1];
__device__ int   g_Gcol[NNZG];
__device__ float g_Gval[NNZG];
__device__ int   g_Hptr[NP+1];
__device__ int   g_Hcur[NP+1];
__device__ int   g_Hcol[NNZH];
__device__ float g_Hval[NNZH];
// filtered user-column edges of G (col < BB)
__device__ int   g_Ecnt[1];
__device__ int   g_Erow[NNZG];
__device__ int   g_Ecol[NNZG];
__device__ float g_Eval[NNZG];

// ---------------- tf32 helpers ----------------------------------------------
__device__ __forceinline__ unsigned f2tf32(float x) {
    unsigned r;
    asm("cvt.rna.tf32.f32 %0, %1;" : "=r"(r) : "f"(x));
    return r;
}
__device__ __forceinline__ void mma8(float* c, const unsigned* a, const unsigned* b) {
    asm("mma.sync.aligned.m16n8k8.row.col.f32.tf32.tf32.f32 "
        "{%0,%1,%2,%3},{%4,%5,%6,%7},{%8,%9},{%0,%1,%2,%3};"
        : "+f"(c[0]), "+f"(c[1]), "+f"(c[2]), "+f"(c[3])
        : "r"(a[0]), "r"(a[1]), "r"(a[2]), "r"(a[3]), "r"(b[0]), "r"(b[1]));
}

// ---------------- CSR build: hist / scan / scatter / filter -----------------
__global__ void k_hist(const int* __restrict__ r, int* __restrict__ c, int n) {
    int i = blockIdx.x * blockDim.x + threadIdx.x;
    if (i < n) atomicAdd(&c[r[i]], 1);
}

__global__ void __launch_bounds__(1024) k_scan(int* cur, int* ptr, int n) {
    __shared__ int wt[32];
    __shared__ int carry_s, chunktot;
    int t = threadIdx.x, warp = t >> 5, lane = t & 31;
    if (t == 0) { carry_s = 0; chunktot = 0; }
    __syncthreads();
    for (int base = 0; base < n; base += 1024) {
        int i = base + t;
        int v = (i < n) ? cur[i] : 0;
        int s = v;
#pragma unroll
        for (int off = 1; off < 32; off <<= 1) {
            int x = __shfl_up_sync(0xffffffffu, s, off);
            if (lane >= off) s += x;
        }
        if (lane == 31) wt[warp] = s;
        __syncthreads();
        if (warp == 0) {
            int x = wt[lane];
            int xi = x;
#pragma unroll
            for (int off = 1; off < 32; off <<= 1) {
                int y = __shfl_up_sync(0xffffffffu, xi, off);
                if (lane >= off) xi += y;
            }
            wt[lane] = xi - x;
            if (lane == 31) chunktot = xi;
        }
        __syncthreads();
        int excl = (s - v) + wt[warp] + carry_s;
        if (i < n) { ptr[i] = excl; cur[i] = excl; }
        __syncthreads();
        if (t == 0) carry_s += chunktot;
        __syncthreads();
    }
    if (t == 0) ptr[n] = carry_s;
}

__global__ void k_scat(const int* __restrict__ r, const int* __restrict__ cl,
                       const float* __restrict__ v, int* __restrict__ cur,
                       int* __restrict__ pc, float* __restrict__ pv, int n) {
    int i = blockIdx.x * blockDim.x + threadIdx.x;
    if (i < n) {
        int p = atomicAdd(&cur[r[i]], 1);
        pc[p] = cl[i]; pv[p] = v[i];
    }
}

__global__ void k_filter(const int* __restrict__ r, const int* __restrict__ cl,
                         const float* __restrict__ v, int n, int* __restrict__ cnt,
                         int* __restrict__ er, int* __restrict__ ec,
                         float* __restrict__ ev) {
    int i = blockIdx.x * blockDim.x + threadIdx.x;
    if (i < n) {
        int c = cl[i];
        if (c < BB) {
            int p = atomicAdd(cnt, 1);
            er[p] = r[i]; ec[p] = c; ev[p] = v[i];
        }
    }
}

// ---------------- CSR spmm, warp per row ------------------------------------
// fused variant (dst + acc) for the H chain
__global__ void k_spmm_csr(const int* __restrict__ ptr, const int* __restrict__ pcol,
                           const float* __restrict__ pval, const float* __restrict__ x,
                           float* __restrict__ dst, float* __restrict__ acc, int nrows) {
    int r = (blockIdx.x * blockDim.x + threadIdx.x) >> 5;
    if (r >= nrows) return;
    int lane = threadIdx.x & 31;
    int beg = __ldg(ptr + r), end = __ldg(ptr + r + 1);
    float4 s = make_float4(0.f, 0.f, 0.f, 0.f);
#pragma unroll 4
    for (int k = beg; k < end; k++) {
        int c = __ldg(pcol + k);
        float v = __ldg(pval + k);
        float4 a = ((const float4*)(x + (size_t)c * D))[lane];
        s.x += v * a.x; s.y += v * a.y; s.z += v * a.z; s.w += v * a.w;
    }
    ((float4*)(dst + (size_t)r * D))[lane] = s;
    float4* ap = (float4*)(acc + (size_t)r * D) + lane;
    float4 av = *ap;
    av.x += s.x; av.y += s.y; av.z += s.z; av.w += s.w;
    *ap = av;
}

// base variant: dst only (acc handled later, after the user-column correction)
__global__ void k_spmm_base(const int* __restrict__ ptr, const int* __restrict__ pcol,
                            const float* __restrict__ pval, const float* __restrict__ x,
                            float* __restrict__ dst, int nrows) {
    int r = (blockIdx.x * blockDim.x + threadIdx.x) >> 5;
    if (r >= nrows) return;
    int lane = threadIdx.x & 31;
    int beg = __ldg(ptr + r), end = __ldg(ptr + r + 1);
    float4 s = make_float4(0.f, 0.f, 0.f, 0.f);
#pragma unroll 4
    for (int k = beg; k < end; k++) {
        int c = __ldg(pcol + k);
        float v = __ldg(pval + k);
        float4 a = ((const float4*)(x + (size_t)c * D))[lane];
        s.x += v * a.x; s.y += v * a.y; s.z += v * a.z; s.w += v * a.w;
    }
    ((float4*)(dst + (size_t)r * D))[lane] = s;
}

// correction: dst[row] += val * (users[col] - oldx[col]) over filtered edges
__global__ void k_corr(const int* __restrict__ er, const int* __restrict__ ec,
                       const float* __restrict__ ev, const int* __restrict__ cnt,
                       const float* __restrict__ users, const float* __restrict__ oldx,
                       float* __restrict__ dst) {
    int w = (blockIdx.x * blockDim.x + threadIdx.x) >> 5;
    int lane = threadIdx.x & 31;
    int n = *cnt;
    int nw = (gridDim.x * blockDim.x) >> 5;
    for (int e = w; e < n; e += nw) {
        int row = __ldg(er + e);
        int col = __ldg(ec + e);
        float v = __ldg(ev + e);
        float4 u = ((const float4*)(users + (size_t)col * D))[lane];
        float4 o = ((const float4*)(oldx + (size_t)col * D))[lane];
        float* dp = dst + (size_t)row * D + lane * 4;
        atomicAdd(dp + 0, v * (u.x - o.x));
        atomicAdd(dp + 1, v * (u.y - o.y));
        atomicAdd(dp + 2, v * (u.z - o.z));
        atomicAdd(dp + 3, v * (u.w - o.w));
    }
}

// acc += src
__global__ void k_accadd(float* __restrict__ acc, const float* __restrict__ src, int n4) {
    int i = blockIdx.x * blockDim.x + threadIdx.x;
    if (i >= n4) return;
    float4 a = ((float4*)acc)[i];
    float4 s = ((const float4*)src)[i];
    a.x += s.x; a.y += s.y; a.z += s.z; a.w += s.w;
    ((float4*)acc)[i] = a;
}

// ---------------- geo bmm: adj streamed from global, seq in smem ------------
#define SEQ_P 136
#define GEOMMA_SM (104*SEQ_P*4)

__global__ void __launch_bounds__(512, 2) k_geo_mma(const float* __restrict__ adj,
                                                    const int* __restrict__ seqs,
                                                    const float* __restrict__ nodes,
                                                    float* __restrict__ seq_out,
                                                    float* __restrict__ geo_out) {
    extern __shared__ unsigned usm[];
    unsigned* sSeq = usm;                    // [104][SEQ_P], rows s, cols d
    int b = blockIdx.x, t = threadIdx.x;
    int warp = t >> 5, lane = t & 31;
    int g = lane >> 2, t4 = lane & 3;

    const int* sq = seqs + (size_t)b * SL;
    float* so = seq_out + (size_t)b * SL * D;
    for (int i = t; i < SL * 32; i += 512) {
        int s = i >> 5, d4 = i & 31;
        int r = __ldg(sq + s);
        float4 v = *(const float4*)(nodes + (size_t)r * D + d4 * 4);
        ((float4*)(so + (size_t)s * D))[d4] = v;
        unsigned* sp = sSeq + s * SEQ_P + d4 * 4;
        sp[0] = f2tf32(v.x); sp[1] = f2tf32(v.y);
        sp[2] = f2tf32(v.z); sp[3] = f2tf32(v.w);
    }
    for (int i = t; i < 4 * SEQ_P; i += 512) {
        sSeq[(SL + i / SEQ_P) * SEQ_P + (i % SEQ_P)] = 0u;
    }
    __syncthreads();

    if (warp < 14) {
        int mt = warp % 7, nh = warp / 7;
        int mbase = mt * 16;
        int row0 = mbase + g, row1 = mbase + 8 + g;
        const float* adjb = adj + (size_t)b * SL * SL;
        float acc[8][4];
#pragma unroll
        for (int nt = 0; nt < 8; nt++)
#pragma unroll
            for (int j = 0; j < 4; j++) acc[nt][j] = 0.f;
#pragma unroll 1
        for (int kc = 0; kc < 13; kc++) {
            int c0 = kc * 8 + t4, c1 = c0 + 4;
            unsigned a[4];
            float v0 = (row0 < SL) ? __ldg(adjb + row0 * SL + c0) : 0.f;
            float v1 = (row1 < SL) ? __ldg(adjb + row1 * SL + c0) : 0.f;
            float v2 = (row0 < SL && c1 < SL) ? __ldg(adjb + row0 * SL + c1) : 0.f;
            float v3 = (row1 < SL && c1 < SL) ? __ldg(adjb + row1 * SL + c1) : 0.f;
            a[0] = f2tf32(v0); a[1] = f2tf32(v1); a[2] = f2tf32(v2); a[3] = f2tf32(v3);
#pragma unroll
            for (int nt = 0; nt < 8; nt++) {
                int nti = nh * 8 + nt;
                unsigned bb[2];
                bb[0] = sSeq[c0 * SEQ_P + nti * 8 + g];
                bb[1] = sSeq[c1 * SEQ_P + nti * 8 + g];
                mma8(acc[nt], a, bb);
            }
        }
        float* gb = geo_out + (size_t)b * SL * D;
#pragma unroll
        for (int nt = 0; nt < 8; nt++) {
            int d = (nh * 8 + nt) * 8 + 2 * t4;
            if (row0 < SL) {
                gb[(size_t)row0 * D + d]     = acc[nt][0];
                gb[(size_t)row0 * D + d + 1] = acc[nt][1];
            }
            if (row1 < SL) {
                gb[(size_t)row1 * D + d]     = acc[nt][2];
                gb[(size_t)row1 * D + d + 1] = acc[nt][3];
            }
        }
    }
}

// ---------------- single-TF32 tensor-core GEMM: C = act(A @ W^T + bias) -----
// ACT: 0 none, 1 relu, 2 tanh, 3 relu then += res[m] + posl[(m%SL+1)],
//      4 tanh with A-load = concat gather [posg[(l+1)*mask[m]] | A[m]] (K=256).
template <int ACT>
__global__ void __launch_bounds__(256) k_gemm(const float* __restrict__ A,
                                              const float* __restrict__ W,
                                              const float* __restrict__ bias,
                                              float* __restrict__ C,
                                              int M, int Nld, int K,
                                              const float* __restrict__ res,
                                              const float* __restrict__ posl,
                                              const int* __restrict__ imask) {
    extern __shared__ unsigned usm[];
    const int KCp = 36;
    unsigned* sA = usm;                      // [128][36] tf32 bits
    unsigned* sW = usm + 128 * KCp;
    int t = threadIdx.x;
    int lane = t & 31, warp = t >> 5;
    int wm = warp & 1, wn = warp >> 1;       // warp tile: 64 M x 32 N
    int g = lane >> 2, t4 = lane & 3;
    int m0 = blockIdx.x * 128, n0 = blockIdx.y * 128;

    float acc[4][4][4];
#pragma unroll
    for (int mi = 0; mi < 4; mi++)
#pragma unroll
        for (int ni = 0; ni < 4; ni++)
#pragma unroll
            for (int j = 0; j < 4; j++) acc[mi][ni][j] = 0.f;

    for (int kc = 0; kc < K; kc += 32) {
        for (int i = t; i < 1024; i += 256) {
            int row = i >> 3, c4 = i & 7;
            int col = kc + c4 * 4;
            float4 va;
            if (ACT == 4) {
                int mrow = m0 + row;
                if (col < 128) {
                    int l = mrow % SL;
                    int pidx = (l + 1) * __ldg(imask + mrow);
                    va = *(const float4*)(res + (size_t)pidx * D + col);
                } else {
                    va = *(const float4*)(A + (size_t)mrow * D + (col - 128));
                }
            } else {
                va = *(const float4*)(A + (size_t)(m0 + row) * K + col);
            }
            float4 vw = *(const float4*)(W + (size_t)(n0 + row) * K + col);
            int off = row * KCp + c4 * 4;
            sA[off + 0] = f2tf32(va.x); sA[off + 1] = f2tf32(va.y);
            sA[off + 2] = f2tf32(va.z); sA[off + 3] = f2tf32(va.w);
            sW[off + 0] = f2tf32(vw.x); sW[off + 1] = f2tf32(vw.y);
            sW[off + 2] = f2tf32(vw.z); sW[off + 3] = f2tf32(vw.w);
        }
        __syncthreads();
#pragma unroll
        for (int ks = 0; ks < 4; ++ks) {
            int k0 = ks * 8 + t4;
            unsigned ah[4][4], bh[4][2];
#pragma unroll
            for (int mi = 0; mi < 4; mi++) {
                int r = (wm * 64 + mi * 16 + g) * KCp + k0;
                ah[mi][0] = sA[r];
                ah[mi][1] = sA[r + 8 * KCp];
                ah[mi][2] = sA[r + 4];
                ah[mi][3] = sA[r + 8 * KCp + 4];
            }
#pragma unroll
            for (int ni = 0; ni < 4; ni++) {
                int r = (wn * 32 + ni * 8 + g) * KCp + k0;
                bh[ni][0] = sW[r];
                bh[ni][1] = sW[r + 4];
            }
#pragma unroll
            for (int mi = 0; mi < 4; mi++)
#pragma unroll
                for (int ni = 0; ni < 4; ni++)
                    mma8(acc[mi][ni], ah[mi], bh[ni]);
        }
        __syncthreads();
    }

#pragma unroll
    for (int mi = 0; mi < 4; mi++) {
        int mrow = m0 + wm * 64 + mi * 16 + g;
        int l0 = mrow % SL, l1 = (mrow + 8) % SL;
#pragma unroll
        for (int ni = 0; ni < 4; ni++) {
            int n = n0 + wn * 32 + ni * 8 + 2 * t4;
            float b0 = bias ? bias[n] : 0.f;
            float b1 = bias ? bias[n + 1] : 0.f;
            float v0 = acc[mi][ni][0] + b0, v1 = acc[mi][ni][1] + b1;
            float v2 = acc[mi][ni][2] + b0, v3 = acc[mi][ni][3] + b1;
            if (ACT == 1) { v0 = fmaxf(v0, 0.f); v1 = fmaxf(v1, 0.f); v2 = fmaxf(v2, 0.f); v3 = fmaxf(v3, 0.f); }
            if (ACT == 2 || ACT == 4) { v0 = tanhf(v0); v1 = tanhf(v1); v2 = tanhf(v2); v3 = tanhf(v3); }
            if (ACT == 3) {
                v0 = fmaxf(v0, 0.f) + res[(size_t)mrow * D + n]       + posl[(l0 + 1) * D + n];
                v1 = fmaxf(v1, 0.f) + res[(size_t)mrow * D + n + 1]   + posl[(l0 + 1) * D + n + 1];
                v2 = fmaxf(v2, 0.f) + res[(size_t)(mrow + 8) * D + n]     + posl[(l1 + 1) * D + n];
                v3 = fmaxf(v3, 0.f) + res[(size_t)(mrow + 8) * D + n + 1] + posl[(l1 + 1) * D + n + 1];
            }
            C[(size_t)mrow * Nld + n]           = v0;
            C[(size_t)mrow * Nld + n + 1]       = v1;
            C[(size_t)(mrow + 8) * Nld + n]     = v2;
            C[(size_t)(mrow + 8) * Nld + n + 1] = v3;
        }
    }
}

// ---------------- tensor-core MHA: one block per (b,h) ----------------------
#define QP 20
#define SP 108
#define OFF_K 2240
#define OFF_VT 4320
#define OFF_S 6048
#define ATTN2_SM ((OFF_S + 112*SP) * 4)

__global__ void __launch_bounds__(512, 2) k_attn_mma(const float* __restrict__ qkv,
                                                     float* __restrict__ o) {
    extern __shared__ unsigned usm[];
    unsigned* sQ  = usm;
    unsigned* sK  = usm + OFF_K;
    unsigned* sVT = usm + OFF_VT;
    float*    sS  = (float*)(usm + OFF_S);
    int b = blockIdx.x >> 3, h = blockIdx.x & 7;
    int t = threadIdx.x;
    int warp = t >> 5, lane = t & 31;
    int g = lane >> 2, t4 = lane & 3;
    const float* base = qkv + (size_t)b * SL * 384 + h * HD;

    if (t < 400) {
        int row = t >> 2, c = t & 3;
        const float* rp = base + (size_t)row * 384;
        float4 qv = *(const float4*)(rp + c * 4);
        float4 kv = *(const float4*)(rp + 128 + c * 4);
        float4 vv = *(const float4*)(rp + 256 + c * 4);
        unsigned* qp = sQ + row * QP + c * 4;
        qp[0] = f2tf32(qv.x * 0.25f); qp[1] = f2tf32(qv.y * 0.25f);
        qp[2] = f2tf32(qv.z * 0.25f); qp[3] = f2tf32(qv.w * 0.25f);
        unsigned* kp = sK + row * QP + c * 4;
        kp[0] = f2tf32(kv.x); kp[1] = f2tf32(kv.y);
        kp[2] = f2tf32(kv.z); kp[3] = f2tf32(kv.w);
        sVT[(c * 4 + 0) * SP + row] = f2tf32(vv.x);
        sVT[(c * 4 + 1) * SP + row] = f2tf32(vv.y);
        sVT[(c * 4 + 2) * SP + row] = f2tf32(vv.z);
        sVT[(c * 4 + 3) * SP + row] = f2tf32(vv.w);
    }
    for (int i = t; i < 12 * QP; i += 512) sQ[(SL + i / QP) * QP + (i % QP)] = 0u;
    for (int i = t; i < 4 * QP; i += 512)  sK[(SL + i / QP) * QP + (i % QP)] = 0u;
    for (int i = t; i < 16 * 4; i += 512)  sVT[(i >> 2) * SP + SL + (i & 3)] = 0u;
    __syncthreads();

    if (warp < 14) {
        int mt = warp % 7, nh = warp / 7;
        int mb = mt * 16;
        int ntn = nh ? 6 : 7;
        int nt0 = nh * 7;
        float sacc[7][4];
#pragma unroll
        for (int j = 0; j < 7; j++)
#pragma unroll
            for (int k = 0; k < 4; k++) sacc[j][k] = 0.f;
#pragma unroll
        for (int kc = 0; kc < 2; kc++) {
            int k0 = kc * 8 + t4;
            unsigned a[4];
            a[0] = sQ[(mb + g) * QP + k0];
            a[1] = sQ[(mb + 8 + g) * QP + k0];
            a[2] = sQ[(mb + g) * QP + k0 + 4];
            a[3] = sQ[(mb + 8 + g) * QP + k0 + 4];
#pragma unroll
            for (int j = 0; j < 7; j++) {
                if (j < ntn) {
                    int nti = nt0 + j;
                    unsigned bb[2];
                    bb[0] = sK[(nti * 8 + g) * QP + k0];
                    bb[1] = sK[(nti * 8 + g) * QP + k0 + 4];
                    mma8(sacc[j], a, bb);
                }
            }
        }
#pragma unroll
        for (int j = 0; j < 7; j++) {
            if (j < ntn) {
                int col = (nt0 + j) * 8 + 2 * t4;
                sS[(mb + g) * SP + col]         = sacc[j][0];
                sS[(mb + g) * SP + col + 1]     = sacc[j][1];
                sS[(mb + 8 + g) * SP + col]     = sacc[j][2];
                sS[(mb + 8 + g) * SP + col + 1] = sacc[j][3];
            }
        }
    }
    __syncthreads();

    if (t < SL) {
        float* srow = sS + t * SP;
        float mx = -3.4e38f;
        for (int j = 0; j < SL; j++) mx = fmaxf(mx, srow[j]);
        float sum = 0.f;
        for (int j = 0; j < SL; j++) {
            float e = __expf(srow[j] - mx);
            srow[j] = e;
            sum += e;
        }
        float inv = 1.0f / sum;
        unsigned* urow = (unsigned*)srow;
        for (int j = 0; j < SL; j++) urow[j] = f2tf32(srow[j] * inv);
        urow[100] = 0u; urow[101] = 0u; urow[102] = 0u; urow[103] = 0u;
    }
    __syncthreads();

    if (warp < 14) {
        int mt = warp % 7, nt = warp / 7;
        int mb = mt * 16;
        const unsigned* uS = (const unsigned*)sS;
        float oacc[4] = {0.f, 0.f, 0.f, 0.f};
#pragma unroll 1
        for (int kc = 0; kc < 13; kc++) {
            int k0 = kc * 8 + t4;
            unsigned a[4], bb[2];
            a[0] = uS[(mb + g) * SP + k0];
            a[1] = uS[(mb + 8 + g) * SP + k0];
            a[2] = uS[(mb + g) * SP + k0 + 4];
            a[3] = uS[(mb + 8 + g) * SP + k0 + 4];
            bb[0] = sVT[(nt * 8 + g) * SP + k0];
            bb[1] = sVT[(nt * 8 + g) * SP + k0 + 4];
            mma8(oacc, a, bb);
        }
        int r0 = mb + g, r1 = mb + 8 + g;
        int col = h * HD + nt * 8 + 2 * t4;
        if (r0 < SL) {
            float* op = o + (size_t)(b * SL + r0) * D + col;
            op[0] = oacc[0]; op[1] = oacc[1];
        }
        if (r1 < SL) {
            float* op = o + (size_t)(b * SL + r1) * D + col;
            op[0] = oacc[2]; op[1] = oacc[3];
        }
    }
}

// ---------------- mean over l into users buffer ------------------------------
__global__ void k_meanuser(const float* __restrict__ x, float* __restrict__ users) {
    int b = blockIdx.x, t = threadIdx.x;
    const float* p = x + (size_t)b * SL * D + t;
    float s = 0.f;
#pragma unroll 4
    for (int l = 0; l < SL; l++) s += p[(size_t)l * D];
    users[(size_t)b * D + t] = s * (1.0f / SL);
}

// ---------------- pois output ------------------------------------------------
__global__ void k_pois(const float* __restrict__ acc, const float* __restrict__ gacc,
                       float* __restrict__ out) {
    int i = blockIdx.x * blockDim.x + threadIdx.x;
    if (i >= NP * D / 4) return;
    float4 a = ((const float4*)(acc + (size_t)NU * D))[i];
    float4 g = ((const float4*)gacc)[i];
    float4 o;
    const float f = 1.0f / 3.0f;
    o.x = (a.x + g.x) * f; o.y = (a.y + g.y) * f;
    o.z = (a.z + g.z) * f; o.w = (a.w + g.w) * f;
    ((float4*)(out + (size_t)BB * D))[i] = o;
}

// ---------------- fused: seq_h gather (fusion on the fly) + hs --------------
__global__ void __launch_bounds__(128) k_fushs(const int* __restrict__ rev,
                                               const float* __restrict__ acc,
                                               const float* __restrict__ gacc,
                                               const float* __restrict__ lens,
                                               float* __restrict__ seqh,
                                               float* __restrict__ hs) {
    int b = blockIdx.x, t = threadIdx.x;
    const int* rb = rev + (size_t)b * SL;
    float* sb = seqh + (size_t)b * SL * D + t;
    const float f = 1.0f / 3.0f;
    float sum = 0.f;
    for (int l = 0; l < SL; l++) {
        int idx = __ldg(rb + l);
        float v = 0.f;
        if (idx < NU) {
            v = acc[(size_t)idx * D + t] * f;
        } else if (idx < NN - 1) {
            v = (acc[(size_t)idx * D + t] + gacc[(size_t)(idx - NU) * D + t]) * f;
        }
        sb[(size_t)l * D] = v;
        sum += v;
    }
    hs[(size_t)b * D + t] = sum / lens[b];
}

// ---------------- fused gate: beta (sigmoid dot) + select + local_users -----
__global__ void __launch_bounds__(128) k_gate(const float* __restrict__ z,
                                              const float* __restrict__ hsg,
                                              const float* __restrict__ w2,
                                              const float* __restrict__ seqh,
                                              const float* __restrict__ acc,
                                              const int* __restrict__ uidx,
                                              float* __restrict__ out) {
    __shared__ float sb[SL];
    int b = blockIdx.x, t = threadIdx.x;
    int warp = t >> 5, lane = t & 31;
    float4 hv = ((const float4*)(hsg + (size_t)b * D))[lane];
    float4 wv = ((const float4*)w2)[lane];
    for (int l = warp; l < SL; l += 4) {
        float4 zv = ((const float4*)(z + (size_t)(b * SL + l) * D))[lane];
        float x0 = 1.0f / (1.0f + __expf(-(zv.x + hv.x)));
        float x1 = 1.0f / (1.0f + __expf(-(zv.y + hv.y)));
        float x2 = 1.0f / (1.0f + __expf(-(zv.z + hv.z)));
        float x3 = 1.0f / (1.0f + __expf(-(zv.w + hv.w)));
        float s = x0 * wv.x + x1 * wv.y + x2 * wv.z + x3 * wv.w;
#pragma unroll
        for (int off = 16; off > 0; off >>= 1) s += __shfl_xor_sync(0xffffffffu, s, off);
        if (lane == 0) sb[l] = s;
    }
    __syncthreads();
    const float* sp = seqh + (size_t)b * SL * D + t;
    float a = 0.f;
#pragma unroll 4
    for (int l = 0; l < SL; l++) a += sb[l] * sp[(size_t)l * D];
    out[(size_t)b * D + t] = a + acc[(size_t)uidx[b] * D + t] * (1.0f / 3.0f);
}

// ============================================================================
extern "C" void kernel_launch(void* const* d_in, const int* in_sizes, int n_in,
                              void* d_out, int out_size) {
    const float* nodes_emb   = (const float*)d_in[0];
    const float* pos_local   = (const float*)d_in[1];
    const float* fc_geo_w    = (const float*)d_in[2];
    const float* fc_geo_b    = (const float*)d_in[3];
    const float* in_proj_w   = (const float*)d_in[4];
    const float* in_proj_b   = (const float*)d_in[5];
    const float* out_proj_w  = (const float*)d_in[6];
    const float* out_proj_b  = (const float*)d_in[7];
    const float* pos_glob    = (const float*)d_in[8];
    const float* w1_w        = (const float*)d_in[9];
    const float* w1_b        = (const float*)d_in[10];
    const float* w_2         = (const float*)d_in[11];
    const float* glu1_w      = (const float*)d_in[12];
    const float* glu1_b      = (const float*)d_in[13];
    const float* glu2_w      = (const float*)d_in[14];
    const int*   G_rows      = (const int*)d_in[15];
    const int*   G_cols      = (const int*)d_in[16];
    const float* G_vals      = (const float*)d_in[17];
    const int*   HG_rows     = (const int*)d_in[18];
    const int*   HG_cols     = (const int*)d_in[19];
    const float* HG_vals     = (const float*)d_in[20];
    const int*   seqs        = (const int*)d_in[21];
    const int*   masks       = (const int*)d_in[22];
    const float* adjs        = (const float*)d_in[23];
    const int*   uidx        = (const int*)d_in[24];
    const float* lens        = (const float*)d_in[25];
    const int*   revs        = (const int*)d_in[26];
    float* out = (float*)d_out;

    float *nodesA, *acc, *nodesB, *gx, *gacc, *gt, *seq, *t1, *t2, *qkv, *o, *users, *hs;
    int *Gptr, *Gcur, *Gcol, *Hptr, *Hcur, *Hcol, *Ecnt, *Erow, *Ecol;
    float *Gval, *Hval, *Eval;
    void* p;
    cudaGetSymbolAddress(&p, g_nodes); nodesA = (float*)p;
    cudaGetSymbolAddress(&p, g_acc);   acc    = (float*)p;
    cudaGetSymbolAddress(&p, g_tmp);   nodesB = (float*)p;
    cudaGetSymbolAddress(&p, g_gx);    gx     = (float*)p;
    cudaGetSymbolAddress(&p, g_gacc);  gacc   = (float*)p;
    cudaGetSymbolAddress(&p, g_gt);    gt     = (float*)p;
    cudaGetSymbolAddress(&p, g_seq);   seq    = (float*)p;
    cudaGetSymbolAddress(&p, g_t1);    t1     = (float*)p;
    cudaGetSymbolAddress(&p, g_t2);    t2     = (float*)p;
    cudaGetSymbolAddress(&p, g_qkv);   qkv    = (float*)p;
    cudaGetSymbolAddress(&p, g_o);     o      = (float*)p;
    cudaGetSymbolAddress(&p, g_users); users  = (float*)p;
    cudaGetSymbolAddress(&p, g_hs);    hs     = (float*)p;
    cudaGetSymbolAddress(&p, g_Gptr);  Gptr   = (int*)p;
    cudaGetSymbolAddress(&p, g_Gcur);  Gcur   = (int*)p;
    cudaGetSymbolAddress(&p, g_Gcol);  Gcol   = (int*)p;
    cudaGetSymbolAddress(&p, g_Gval);  Gval   = (float*)p;
    cudaGetSymbolAddress(&p, g_Hptr);  Hptr   = (int*)p;
    cudaGetSymbolAddress(&p, g_Hcur);  Hcur   = (int*)p;
    cudaGetSymbolAddress(&p, g_Hcol);  Hcol   = (int*)p;
    cudaGetSymbolAddress(&p, g_Hval);  Hval   = (float*)p;
    cudaGetSymbolAddress(&p, g_Ecnt);  Ecnt   = (int*)p;
    cudaGetSymbolAddress(&p, g_Erow);  Erow   = (int*)p;
    cudaGetSymbolAddress(&p, g_Ecol);  Ecol   = (int*)p;
    cudaGetSymbolAddress(&p, g_Eval);  Eval   = (float*)p;

    const int GEMM_SM = 2 * 128 * 36 * 4;                   // 36864
    cudaFuncSetAttribute((const void*)k_geo_mma,  cudaFuncAttributeMaxDynamicSharedMemorySize, GEOMMA_SM);
    cudaFuncSetAttribute((const void*)k_attn_mma, cudaFuncAttributeMaxDynamicSharedMemorySize, ATTN2_SM);
    cudaFuncSetAttribute((const void*)k_gemm<0>,  cudaFuncAttributeMaxDynamicSharedMemorySize, GEMM_SM);
    cudaFuncSetAttribute((const void*)k_gemm<3>,  cudaFuncAttributeMaxDynamicSharedMemorySize, GEMM_SM);
    cudaFuncSetAttribute((const void*)k_gemm<4>,  cudaFuncAttributeMaxDynamicSharedMemorySize, GEMM_SM);

    const int M128 = MROWS / 128;          // 800
    const float* nullf = (const float*)0;
    const int*   nulli = (const int*)0;

    // persistent streams/events (created once on the correctness call so their
    // lazy device allocations land inside the pre-capture baseline)
    static cudaStream_t sA = 0, sB = 0, sC = 0;
    static cudaEvent_t evFork = 0, evG = 0, evH = 0, evInit = 0, evS0 = 0, evS1 = 0, evL0 = 0;
    if (sA == 0) {
        cudaStreamCreateWithFlags(&sA, cudaStreamNonBlocking);
        cudaStreamCreateWithFlags(&sB, cudaStreamNonBlocking);
        cudaStreamCreateWithFlags(&sC, cudaStreamNonBlocking);
        cudaEventCreateWithFlags(&evFork, cudaEventDisableTiming);
        cudaEventCreateWithFlags(&evG,    cudaEventDisableTiming);
        cudaEventCreateWithFlags(&evH,    cudaEventDisableTiming);
        cudaEventCreateWithFlags(&evInit, cudaEventDisableTiming);
        cudaEventCreateWithFlags(&evS0,   cudaEventDisableTiming);
        cudaEventCreateWithFlags(&evS1,   cudaEventDisableTiming);
        cudaEventCreateWithFlags(&evL0,   cudaEventDisableTiming);
    }

    cudaEventRecord(evFork, 0);
    cudaStreamWaitEvent(sA, evFork, 0);
    cudaStreamWaitEvent(sB, evFork, 0);
    cudaStreamWaitEvent(sC, evFork, 0);

    // ---- stream A: CSR-G build + user-column edge filter ----
    cudaMemsetAsync(Gcur, 0, (NGROWS + 1) * sizeof(int), sA);
    cudaMemsetAsync(Ecnt, 0, sizeof(int), sA);
    k_hist<<<(NNZG + 255) / 256, 256, 0, sA>>>(G_rows, Gcur, NNZG);
    k_scan<<<1, 1024, 0, sA>>>(Gcur, Gptr, NGROWS);
    k_scat<<<(NNZG + 255) / 256, 256, 0, sA>>>(G_rows, G_cols, G_vals, Gcur, Gcol, Gval, NNZG);
    k_filter<<<(NNZG + 255) / 256, 256, 0, sA>>>(G_rows, G_cols, G_vals, NNZG, Ecnt, Erow, Ecol, Eval);
    cudaEventRecord(evG, sA);

    // ---- stream B: full hypergraph chain ----
    cudaMemcpyAsync(gx,   nodes_emb + (size_t)NU * D, (size_t)NP * D * 4, cudaMemcpyDeviceToDevice, sB);
    cudaMemcpyAsync(gacc, nodes_emb + (size_t)NU * D, (size_t)NP * D * 4, cudaMemcpyDeviceToDevice, sB);
    cudaMemsetAsync(Hcur, 0, (NP + 1) * sizeof(int), sB);
    k_hist<<<(NNZH + 255) / 256, 256, 0, sB>>>(HG_rows, Hcur, NNZH);
    k_scan<<<1, 1024, 0, sB>>>(Hcur, Hptr, NP);
    k_scat<<<(NNZH + 255) / 256, 256, 0, sB>>>(HG_rows, HG_cols, HG_vals, Hcur, Hcol, Hval, NNZH);
    k_spmm_csr<<<(NP + 7) / 8, 256, 0, sB>>>(Hptr, Hcol, Hval, gx, gt, gacc, NP);
    k_spmm_csr<<<(NP + 7) / 8, 256, 0, sB>>>(Hptr, Hcol, Hval, gt, gx, gacc, NP);
    cudaEventRecord(evH, sB);

    // ---- main stream: init ----
    cudaMemcpyAsync(nodesA, nodes_emb, (size_t)NN * D * 4, cudaMemcpyDeviceToDevice, 0);
    cudaMemcpyAsync(acc,    nodes_emb, (size_t)NN * D * 4, cudaMemcpyDeviceToDevice, 0);
    cudaEventRecord(evInit, 0);

    // ---- stream C: layer-0 base spmm (G @ nodesA -> nodesB), overlapped ----
    cudaStreamWaitEvent(sC, evG, 0);
    cudaStreamWaitEvent(sC, evInit, 0);
    k_spmm_base<<<(NGROWS + 7) / 8, 256, 0, sC>>>(Gptr, Gcol, Gval, nodesA, nodesB, NGROWS);
    cudaEventRecord(evS0, sC);

    // ---- layer 0 (cur = A, nxt = B) ----
    k_geo_mma<<<BB, 512, GEOMMA_SM>>>(adjs, seqs, nodesA, seq, t1);
    k_gemm<3><<<dim3(M128, 1), 256, GEMM_SM>>>(t1, fc_geo_w, fc_geo_b, t1, MROWS, 128, 128, seq, pos_local, nulli);
    k_gemm<0><<<dim3(M128, 3), 256, GEMM_SM>>>(t1, in_proj_w, in_proj_b, qkv, MROWS, 384, 128, nullf, nullf, nulli);
    k_attn_mma<<<BB * NHD, 512, ATTN2_SM>>>(qkv, o);
    k_gemm<0><<<dim3(M128, 1), 256, GEMM_SM>>>(o, out_proj_w, out_proj_b, t2, MROWS, 128, 128, nullf, nullf, nulli);
    k_meanuser<<<BB, 128>>>(t2, users);
    cudaStreamWaitEvent(0, evS0, 0);
    k_corr<<<512, 256>>>(Erow, Ecol, Eval, Ecnt, users, nodesA, nodesB);
    k_accadd<<<((NN - 1) * D / 4 + 255) / 256, 256>>>(acc, nodesB, (NN - 1) * D / 4);
    cudaEventRecord(evL0, 0);

    // ---- stream C: layer-1 base spmm (G @ nodesB -> nodesA), overlapped ----
    cudaStreamWaitEvent(sC, evL0, 0);
    k_spmm_base<<<(NGROWS + 7) / 8, 256, 0, sC>>>(Gptr, Gcol, Gval, nodesB, nodesA, NGROWS);
    cudaEventRecord(evS1, sC);

    // ---- layer 1 (cur = B, nxt = A) ----
    k_geo_mma<<<BB, 512, GEOMMA_SM>>>(adjs, seqs, nodesB, seq, t1);
    k_gemm<3><<<dim3(M128, 1), 256, GEMM_SM>>>(t1, fc_geo_w, fc_geo_b, t1, MROWS, 128, 128, seq, pos_local, nulli);
    k_gemm<0><<<dim3(M128, 3), 256, GEMM_SM>>>(t1, in_proj_w, in_proj_b, qkv, MROWS, 384, 128, nullf, nullf, nulli);
    k_attn_mma<<<BB * NHD, 512, ATTN2_SM>>>(qkv, o);
    k_gemm<0><<<dim3(M128, 1), 256, GEMM_SM>>>(o, out_proj_w, out_proj_b, t2, MROWS, 128, 128, nullf, nullf, nulli);
    k_meanuser<<<BB, 128>>>(t2, users);
    cudaStreamWaitEvent(0, evS1, 0);
    k_corr<<<512, 256>>>(Erow, Ecol, Eval, Ecnt, users, nodesB, nodesA);
    k_accadd<<<((NN - 1) * D / 4 + 255) / 256, 256>>>(acc, nodesA, (NN - 1) * D / 4);

    // ---- join hypergraph chain, outputs ----
    cudaStreamWaitEvent(0, evH, 0);
    k_pois<<<(NP * D / 4 + 255) / 256, 256>>>(acc, gacc, out);

    // ---- final gated readout (concat fused into w1 gemm, ACT=4) ----
    k_fushs<<<BB, 128>>>(revs, acc, gacc, lens, seq, hs);
    k_gemm<4><<<dim3(M128, 1), 256, GEMM_SM>>>(seq, w1_w, w1_b, t1, MROWS, 128, 256, pos_glob, nullf, masks);
    k_gemm<0><<<dim3(M128, 1), 256, GEMM_SM>>>(t1, glu1_w, glu1_b, t2, MROWS, 128, 128, nullf, nullf, nulli);
    k_gemm<0><<<dim3(BB / 128, 1), 256, GEMM_SM>>>(hs, glu2_w, nullf, users, BB, 128, 128, nullf, nullf, nulli);
    k_gate<<<BB, 128>>>(t2, users, w_2, seq, acc, uidx, out);
}

// round 16
// speedup vs baseline: 1.0854x; 1.0854x over previous
#include <cuda_runtime.h>
#include <math.h>

#define NU 10000
#define NP 50000
#define SL 100
#define D  128
#define NHD 8
#define HD 16
#define NN 60001
#define BB 1024
#define NNZG 1920000
#define NNZH 1600000
#define MROWS (BB*SL)
#define NGROWS 60000

// ---------------- scratch (static device globals; no allocs) ----------------
__device__ float g_nodes[NN*D];       // node buffer A
__device__ float g_acc[NN*D];
__device__ float g_tmp[(NN-1)*D];     // node buffer B
__device__ float g_gx[NP*D];
__device__ float g_gacc[NP*D];
__device__ float g_gt[NP*D];
__device__ float g_seq[MROWS*D];      // seq_e / seq_h
__device__ float g_t1[MROWS*D];       // geo out / tot / nh1
__device__ float g_t2[MROWS*D];       // glu1 out
__device__ float g_qkv[MROWS*3*D];    // qkv
__device__ float g_o[MROWS*D];        // attn mean (BB*D used)
__device__ float g_users[BB*D];       // projected users / hs@glu2
__device__ float g_hs[BB*D];
// CSR scratch
__device__ int   g_Gptr[NGROWS+1];
__device__ int   g_Gcur[NGROWS+1];
__device__ int   g_Gcol[NNZG];
__device__ float g_Gval[NNZG];
__device__ int   g_Hptr[NP+1];
__device__ int   g_Hcur[NP+1];
__device__ int   g_Hcol[NNZH];
__device__ float g_Hval[NNZH];

// ---------------- tf32 helpers ----------------------------------------------
__device__ __forceinline__ unsigned f2tf32(float x) {
    unsigned r;
    asm("cvt.rna.tf32.f32 %0, %1;" : "=r"(r) : "f"(x));
    return r;
}
__device__ __forceinline__ void mma8(float* c, const unsigned* a, const unsigned* b) {
    asm("mma.sync.aligned.m16n8k8.row.col.f32.tf32.tf32.f32 "
        "{%0,%1,%2,%3},{%4,%5,%6,%7},{%8,%9},{%0,%1,%2,%3};"
        : "+f"(c[0]), "+f"(c[1]), "+f"(c[2]), "+f"(c[3])
        : "r"(a[0]), "r"(a[1]), "r"(a[2]), "r"(a[3]), "r"(b[0]), "r"(b[1]));
}

// ---------------- CSR build: hist / scan / scatter (single matrix) ----------
__global__ void k_hist(const int* __restrict__ r, int* __restrict__ c, int n) {
    int i = blockIdx.x * blockDim.x + threadIdx.x;
    if (i < n) atomicAdd(&c[r[i]], 1);
}

__global__ void __launch_bounds__(1024) k_scan(int* cur, int* ptr, int n) {
    __shared__ int wt[32];
    __shared__ int carry_s, chunktot;
    int t = threadIdx.x, warp = t >> 5, lane = t & 31;
    if (t == 0) { carry_s = 0; chunktot = 0; }
    __syncthreads();
    for (int base = 0; base < n; base += 1024) {
        int i = base + t;
        int v = (i < n) ? cur[i] : 0;
        int s = v;
#pragma unroll
        for (int off = 1; off < 32; off <<= 1) {
            int x = __shfl_up_sync(0xffffffffu, s, off);
            if (lane >= off) s += x;
        }
        if (lane == 31) wt[warp] = s;
        __syncthreads();
        if (warp == 0) {
            int x = wt[lane];
            int xi = x;
#pragma unroll
            for (int off = 1; off < 32; off <<= 1) {
                int y = __shfl_up_sync(0xffffffffu, xi, off);
                if (lane >= off) xi += y;
            }
            wt[lane] = xi - x;
            if (lane == 31) chunktot = xi;
        }
        __syncthreads();
        int excl = (s - v) + wt[warp] + carry_s;
        if (i < n) { ptr[i] = excl; cur[i] = excl; }
        __syncthreads();
        if (t == 0) carry_s += chunktot;
        __syncthreads();
    }
    if (t == 0) ptr[n] = carry_s;
}

__global__ void k_scat(const int* __restrict__ r, const int* __restrict__ cl,
                       const float* __restrict__ v, int* __restrict__ cur,
                       int* __restrict__ pc, float* __restrict__ pv, int n) {
    int i = blockIdx.x * blockDim.x + threadIdx.x;
    if (i < n) {
        int p = atomicAdd(&cur[r[i]], 1);
        pc[p] = cl[i]; pv[p] = v[i];
    }
}

// ---------------- CSR spmm, warp per row; fused commit + acc ----------------
__global__ void k_spmm_csr(const int* __restrict__ ptr, const int* __restrict__ pcol,
                           const float* __restrict__ pval, const float* __restrict__ x,
                           float* __restrict__ dst, float* __restrict__ acc, int nrows) {
    int r = (blockIdx.x * blockDim.x + threadIdx.x) >> 5;
    if (r >= nrows) return;
    int lane = threadIdx.x & 31;
    int beg = __ldg(ptr + r), end = __ldg(ptr + r + 1);
    float4 s = make_float4(0.f, 0.f, 0.f, 0.f);
#pragma unroll 4
    for (int k = beg; k < end; k++) {
        int c = __ldg(pcol + k);
        float v = __ldg(pval + k);
        float4 a = ((const float4*)(x + (size_t)c * D))[lane];
        s.x += v * a.x; s.y += v * a.y; s.z += v * a.z; s.w += v * a.w;
    }
    ((float4*)(dst + (size_t)r * D))[lane] = s;
    float4* ap = (float4*)(acc + (size_t)r * D) + lane;
    float4 av = *ap;
    av.x += s.x; av.y += s.y; av.z += s.z; av.w += s.w;
    *ap = av;
}

// ---------------- geo bmm: adj streamed from global, seq in smem ------------
#define SEQ_P 136
#define GEOMMA_SM (104*SEQ_P*4)

__global__ void __launch_bounds__(512, 2) k_geo_mma(const float* __restrict__ adj,
                                                    const int* __restrict__ seqs,
                                                    const float* __restrict__ nodes,
                                                    float* __restrict__ seq_out,
                                                    float* __restrict__ geo_out) {
    extern __shared__ unsigned usm[];
    unsigned* sSeq = usm;                    // [104][SEQ_P], rows s, cols d
    int b = blockIdx.x, t = threadIdx.x;
    int warp = t >> 5, lane = t & 31;
    int g = lane >> 2, t4 = lane & 3;

    const int* sq = seqs + (size_t)b * SL;
    float* so = seq_out + (size_t)b * SL * D;
    for (int i = t; i < SL * 32; i += 512) {
        int s = i >> 5, d4 = i & 31;
        int r = __ldg(sq + s);
        float4 v = *(const float4*)(nodes + (size_t)r * D + d4 * 4);
        ((float4*)(so + (size_t)s * D))[d4] = v;
        unsigned* sp = sSeq + s * SEQ_P + d4 * 4;
        sp[0] = f2tf32(v.x); sp[1] = f2tf32(v.y);
        sp[2] = f2tf32(v.z); sp[3] = f2tf32(v.w);
    }
    for (int i = t; i < 4 * SEQ_P; i += 512) {
        sSeq[(SL + i / SEQ_P) * SEQ_P + (i % SEQ_P)] = 0u;
    }
    __syncthreads();

    if (warp < 14) {
        int mt = warp % 7, nh = warp / 7;
        int mbase = mt * 16;
        int row0 = mbase + g, row1 = mbase + 8 + g;
        const float* adjb = adj + (size_t)b * SL * SL;
        float acc[8][4];
#pragma unroll
        for (int nt = 0; nt < 8; nt++)
#pragma unroll
            for (int j = 0; j < 4; j++) acc[nt][j] = 0.f;
#pragma unroll 1
        for (int kc = 0; kc < 13; kc++) {
            int c0 = kc * 8 + t4, c1 = c0 + 4;
            unsigned a[4];
            float v0 = (row0 < SL) ? __ldg(adjb + row0 * SL + c0) : 0.f;
            float v1 = (row1 < SL) ? __ldg(adjb + row1 * SL + c0) : 0.f;
            float v2 = (row0 < SL && c1 < SL) ? __ldg(adjb + row0 * SL + c1) : 0.f;
            float v3 = (row1 < SL && c1 < SL) ? __ldg(adjb + row1 * SL + c1) : 0.f;
            a[0] = f2tf32(v0); a[1] = f2tf32(v1); a[2] = f2tf32(v2); a[3] = f2tf32(v3);
#pragma unroll
            for (int nt = 0; nt < 8; nt++) {
                int nti = nh * 8 + nt;
                unsigned bb[2];
                bb[0] = sSeq[c0 * SEQ_P + nti * 8 + g];
                bb[1] = sSeq[c1 * SEQ_P + nti * 8 + g];
                mma8(acc[nt], a, bb);
            }
        }
        float* gb = geo_out + (size_t)b * SL * D;
#pragma unroll
        for (int nt = 0; nt < 8; nt++) {
            int d = (nh * 8 + nt) * 8 + 2 * t4;
            if (row0 < SL) {
                gb[(size_t)row0 * D + d]     = acc[nt][0];
                gb[(size_t)row0 * D + d + 1] = acc[nt][1];
            }
            if (row1 < SL) {
                gb[(size_t)row1 * D + d]     = acc[nt][2];
                gb[(size_t)row1 * D + d + 1] = acc[nt][3];
            }
        }
    }
}

// ---------------- single-TF32 tensor-core GEMM: C = act(A @ W^T + bias) -----
// ACT: 0 none, 1 relu, 2 tanh, 3 relu then += res[m] + posl[(m%SL+1)],
//      4 tanh with A-load = concat gather [posg[(l+1)*mask[m]] | A[m]] (K=256).
template <int ACT>
__global__ void __launch_bounds__(256) k_gemm(const float* __restrict__ A,
                                              const float* __restrict__ W,
                                              const float* __restrict__ bias,
                                              float* __restrict__ C,
                                              int M, int Nld, int K,
                                              const float* __restrict__ res,
                                              const float* __restrict__ posl,
                                              const int* __restrict__ imask) {
    extern __shared__ unsigned usm[];
    const int KCp = 36;
    unsigned* sA = usm;                      // [128][36] tf32 bits
    unsigned* sW = usm + 128 * KCp;
    int t = threadIdx.x;
    int lane = t & 31, warp = t >> 5;
    int wm = warp & 1, wn = warp >> 1;       // warp tile: 64 M x 32 N
    int g = lane >> 2, t4 = lane & 3;
    int m0 = blockIdx.x * 128, n0 = blockIdx.y * 128;

    float acc[4][4][4];
#pragma unroll
    for (int mi = 0; mi < 4; mi++)
#pragma unroll
        for (int ni = 0; ni < 4; ni++)
#pragma unroll
            for (int j = 0; j < 4; j++) acc[mi][ni][j] = 0.f;

    for (int kc = 0; kc < K; kc += 32) {
        for (int i = t; i < 1024; i += 256) {
            int row = i >> 3, c4 = i & 7;
            int col = kc + c4 * 4;
            float4 va;
            if (ACT == 4) {
                int mrow = m0 + row;
                if (col < 128) {
                    int l = mrow % SL;
                    int pidx = (l + 1) * __ldg(imask + mrow);
                    va = *(const float4*)(res + (size_t)pidx * D + col);
                } else {
                    va = *(const float4*)(A + (size_t)mrow * D + (col - 128));
                }
            } else {
                int mrow = m0 + row;
                va = (mrow < M) ? *(const float4*)(A + (size_t)mrow * K + col)
                                : make_float4(0.f, 0.f, 0.f, 0.f);
            }
            float4 vw = *(const float4*)(W + (size_t)(n0 + row) * K + col);
            int off = row * KCp + c4 * 4;
            sA[off + 0] = f2tf32(va.x); sA[off + 1] = f2tf32(va.y);
            sA[off + 2] = f2tf32(va.z); sA[off + 3] = f2tf32(va.w);
            sW[off + 0] = f2tf32(vw.x); sW[off + 1] = f2tf32(vw.y);
            sW[off + 2] = f2tf32(vw.z); sW[off + 3] = f2tf32(vw.w);
        }
        __syncthreads();
#pragma unroll
        for (int ks = 0; ks < 4; ++ks) {
            int k0 = ks * 8 + t4;
            unsigned ah[4][4], bh[4][2];
#pragma unroll
            for (int mi = 0; mi < 4; mi++) {
                int r = (wm * 64 + mi * 16 + g) * KCp + k0;
                ah[mi][0] = sA[r];
                ah[mi][1] = sA[r + 8 * KCp];
                ah[mi][2] = sA[r + 4];
                ah[mi][3] = sA[r + 8 * KCp + 4];
            }
#pragma unroll
            for (int ni = 0; ni < 4; ni++) {
                int r = (wn * 32 + ni * 8 + g) * KCp + k0;
                bh[ni][0] = sW[r];
                bh[ni][1] = sW[r + 4];
            }
#pragma unroll
            for (int mi = 0; mi < 4; mi++)
#pragma unroll
                for (int ni = 0; ni < 4; ni++)
                    mma8(acc[mi][ni], ah[mi], bh[ni]);
        }
        __syncthreads();
    }

#pragma unroll
    for (int mi = 0; mi < 4; mi++) {
        int mrow = m0 + wm * 64 + mi * 16 + g;
        if (mrow >= M) continue;
        int l0 = mrow % SL, l1 = (mrow + 8) % SL;
        bool ok1 = (mrow + 8) < M;
#pragma unroll
        for (int ni = 0; ni < 4; ni++) {
            int n = n0 + wn * 32 + ni * 8 + 2 * t4;
            float b0 = bias ? bias[n] : 0.f;
            float b1 = bias ? bias[n + 1] : 0.f;
            float v0 = acc[mi][ni][0] + b0, v1 = acc[mi][ni][1] + b1;
            float v2 = acc[mi][ni][2] + b0, v3 = acc[mi][ni][3] + b1;
            if (ACT == 1) { v0 = fmaxf(v0, 0.f); v1 = fmaxf(v1, 0.f); v2 = fmaxf(v2, 0.f); v3 = fmaxf(v3, 0.f); }
            if (ACT == 2 || ACT == 4) { v0 = tanhf(v0); v1 = tanhf(v1); v2 = tanhf(v2); v3 = tanhf(v3); }
            if (ACT == 3) {
                v0 = fmaxf(v0, 0.f) + res[(size_t)mrow * D + n]       + posl[(l0 + 1) * D + n];
                v1 = fmaxf(v1, 0.f) + res[(size_t)mrow * D + n + 1]   + posl[(l0 + 1) * D + n + 1];
                v2 = fmaxf(v2, 0.f) + res[(size_t)(mrow + 8) * D + n]     + posl[(l1 + 1) * D + n];
                v3 = fmaxf(v3, 0.f) + res[(size_t)(mrow + 8) * D + n + 1] + posl[(l1 + 1) * D + n + 1];
            }
            C[(size_t)mrow * Nld + n]     = v0;
            C[(size_t)mrow * Nld + n + 1] = v1;
            if (ok1) {
                C[(size_t)(mrow + 8) * Nld + n]     = v2;
                C[(size_t)(mrow + 8) * Nld + n + 1] = v3;
            }
        }
    }
}

// ---------------- tensor-core MHA with fused row-mean -----------------------
// One block per (b,h). QK^T -> softmax -> P@V, then the block reduces its
// output over rows (each block owns cols h*16..h*16+15 of batch b) and writes
// umean[b, h*16+c] = sum_l o[b,l,c] / SL. No full o tensor materialized.
#define QP 20
#define SP 108
#define OFF_K 2240
#define OFF_VT 4320
#define OFF_S 6048
#define OFF_O (OFF_S + 112*SP)
#define ATTN2_SM ((OFF_O + 16) * 4)

__global__ void __launch_bounds__(512, 2) k_attn_mma(const float* __restrict__ qkv,
                                                     float* __restrict__ umean) {
    extern __shared__ unsigned usm[];
    unsigned* sQ  = usm;
    unsigned* sK  = usm + OFF_K;
    unsigned* sVT = usm + OFF_VT;
    float*    sS  = (float*)(usm + OFF_S);
    float*    sO  = (float*)(usm + OFF_O);   // [16] column sums
    int b = blockIdx.x >> 3, h = blockIdx.x & 7;
    int t = threadIdx.x;
    int warp = t >> 5, lane = t & 31;
    int g = lane >> 2, t4 = lane & 3;
    const float* base = qkv + (size_t)b * SL * 384 + h * HD;

    if (t < 400) {
        int row = t >> 2, c = t & 3;
        const float* rp = base + (size_t)row * 384;
        float4 qv = *(const float4*)(rp + c * 4);
        float4 kv = *(const float4*)(rp + 128 + c * 4);
        float4 vv = *(const float4*)(rp + 256 + c * 4);
        unsigned* qp = sQ + row * QP + c * 4;
        qp[0] = f2tf32(qv.x * 0.25f); qp[1] = f2tf32(qv.y * 0.25f);
        qp[2] = f2tf32(qv.z * 0.25f); qp[3] = f2tf32(qv.w * 0.25f);
        unsigned* kp = sK + row * QP + c * 4;
        kp[0] = f2tf32(kv.x); kp[1] = f2tf32(kv.y);
        kp[2] = f2tf32(kv.z); kp[3] = f2tf32(kv.w);
        sVT[(c * 4 + 0) * SP + row] = f2tf32(vv.x);
        sVT[(c * 4 + 1) * SP + row] = f2tf32(vv.y);
        sVT[(c * 4 + 2) * SP + row] = f2tf32(vv.z);
        sVT[(c * 4 + 3) * SP + row] = f2tf32(vv.w);
    }
    for (int i = t; i < 12 * QP; i += 512) sQ[(SL + i / QP) * QP + (i % QP)] = 0u;
    for (int i = t; i < 4 * QP; i += 512)  sK[(SL + i / QP) * QP + (i % QP)] = 0u;
    for (int i = t; i < 16 * 4; i += 512)  sVT[(i >> 2) * SP + SL + (i & 3)] = 0u;
    if (t >= 496) sO[t - 496] = 0.f;
    __syncthreads();

    if (warp < 14) {
        int mt = warp % 7, nh = warp / 7;
        int mb = mt * 16;
        int ntn = nh ? 6 : 7;
        int nt0 = nh * 7;
        float sacc[7][4];
#pragma unroll
        for (int j = 0; j < 7; j++)
#pragma unroll
            for (int k = 0; k < 4; k++) sacc[j][k] = 0.f;
#pragma unroll
        for (int kc = 0; kc < 2; kc++) {
            int k0 = kc * 8 + t4;
            unsigned a[4];
            a[0] = sQ[(mb + g) * QP + k0];
            a[1] = sQ[(mb + 8 + g) * QP + k0];
            a[2] = sQ[(mb + g) * QP + k0 + 4];
            a[3] = sQ[(mb + 8 + g) * QP + k0 + 4];
#pragma unroll
            for (int j = 0; j < 7; j++) {
                if (j < ntn) {
                    int nti = nt0 + j;
                    unsigned bb[2];
                    bb[0] = sK[(nti * 8 + g) * QP + k0];
                    bb[1] = sK[(nti * 8 + g) * QP + k0 + 4];
                    mma8(sacc[j], a, bb);
                }
            }
        }
#pragma unroll
        for (int j = 0; j < 7; j++) {
            if (j < ntn) {
                int col = (nt0 + j) * 8 + 2 * t4;
                sS[(mb + g) * SP + col]         = sacc[j][0];
                sS[(mb + g) * SP + col + 1]     = sacc[j][1];
                sS[(mb + 8 + g) * SP + col]     = sacc[j][2];
                sS[(mb + 8 + g) * SP + col + 1] = sacc[j][3];
            }
        }
    }
    __syncthreads();

    if (t < SL) {
        float* srow = sS + t * SP;
        float mx = -3.4e38f;
        for (int j = 0; j < SL; j++) mx = fmaxf(mx, srow[j]);
        float sum = 0.f;
        for (int j = 0; j < SL; j++) {
            float e = __expf(srow[j] - mx);
            srow[j] = e;
            sum += e;
        }
        float inv = 1.0f / sum;
        unsigned* urow = (unsigned*)srow;
        for (int j = 0; j < SL; j++) urow[j] = f2tf32(srow[j] * inv);
        urow[100] = 0u; urow[101] = 0u; urow[102] = 0u; urow[103] = 0u;
    }
    __syncthreads();

    if (warp < 14) {
        int mt = warp % 7, nt = warp / 7;
        int mb = mt * 16;
        const unsigned* uS = (const unsigned*)sS;
        float oacc[4] = {0.f, 0.f, 0.f, 0.f};
#pragma unroll 1
        for (int kc = 0; kc < 13; kc++) {
            int k0 = kc * 8 + t4;
            unsigned a[4], bb[2];
            a[0] = uS[(mb + g) * SP + k0];
            a[1] = uS[(mb + 8 + g) * SP + k0];
            a[2] = uS[(mb + g) * SP + k0 + 4];
            a[3] = uS[(mb + 8 + g) * SP + k0 + 4];
            bb[0] = sVT[(nt * 8 + g) * SP + k0];
            bb[1] = sVT[(nt * 8 + g) * SP + k0 + 4];
            mma8(oacc, a, bb);
        }
        // rows >= SL contribute exactly 0 (padded P rows are zero), so sum
        // both rows of every lane and reduce across the 8 g-lanes.
        float c0 = oacc[0] + oacc[2];
        float c1 = oacc[1] + oacc[3];
#pragma unroll
        for (int off = 16; off >= 4; off >>= 1) {
            c0 += __shfl_down_sync(0xffffffffu, c0, off);
            c1 += __shfl_down_sync(0xffffffffu, c1, off);
        }
        if (lane < 4) {
            atomicAdd(&sO[nt * 8 + 2 * lane],     c0);
            atomicAdd(&sO[nt * 8 + 2 * lane + 1], c1);
        }
    }
    __syncthreads();
    if (t < 16) {
        umean[(size_t)b * D + h * HD + t] = sO[t] * (1.0f / SL);
    }
}

// ---------------- scatter projected users into node rows ---------------------
__global__ void k_scatteru(const float* __restrict__ users, const int* __restrict__ uidx,
                           float* __restrict__ nodes) {
    int b = blockIdx.x, t = threadIdx.x;
    nodes[(size_t)uidx[b] * D + t] = users[(size_t)b * D + t];
}

// ---------------- pois output ------------------------------------------------
__global__ void k_pois(const float* __restrict__ acc, const float* __restrict__ gacc,
                       float* __restrict__ out) {
    int i = blockIdx.x * blockDim.x + threadIdx.x;
    if (i >= NP * D / 4) return;
    float4 a = ((const float4*)(acc + (size_t)NU * D))[i];
    float4 g = ((const float4*)gacc)[i];
    float4 o;
    const float f = 1.0f / 3.0f;
    o.x = (a.x + g.x) * f; o.y = (a.y + g.y) * f;
    o.z = (a.z + g.z) * f; o.w = (a.w + g.w) * f;
    ((float4*)(out + (size_t)BB * D))[i] = o;
}

// ---------------- fused: seq_h gather (fusion on the fly) + hs --------------
__global__ void __launch_bounds__(128) k_fushs(const int* __restrict__ rev,
                                               const float* __restrict__ acc,
                                               const float* __restrict__ gacc,
                                               const float* __restrict__ lens,
                                               float* __restrict__ seqh,
                                               float* __restrict__ hs) {
    int b = blockIdx.x, t = threadIdx.x;
    const int* rb = rev + (size_t)b * SL;
    float* sb = seqh + (size_t)b * SL * D + t;
    const float f = 1.0f / 3.0f;
    float sum = 0.f;
    for (int l = 0; l < SL; l++) {
        int idx = __ldg(rb + l);
        float v = 0.f;
        if (idx < NU) {
            v = acc[(size_t)idx * D + t] * f;
        } else if (idx < NN - 1) {
            v = (acc[(size_t)idx * D + t] + gacc[(size_t)(idx - NU) * D + t]) * f;
        }
        sb[(size_t)l * D] = v;
        sum += v;
    }
    hs[(size_t)b * D + t] = sum / lens[b];
}

// ---------------- fused gate: beta (sigmoid dot) + select + local_users -----
__global__ void __launch_bounds__(128) k_gate(const float* __restrict__ z,
                                              const float* __restrict__ hsg,
                                              const float* __restrict__ w2,
                                              const float* __restrict__ seqh,
                                              const float* __restrict__ acc,
                                              const int* __restrict__ uidx,
                                              float* __restrict__ out) {
    __shared__ float sb[SL];
    int b = blockIdx.x, t = threadIdx.x;
    int warp = t >> 5, lane = t & 31;
    float4 hv = ((const float4*)(hsg + (size_t)b * D))[lane];
    float4 wv = ((const float4*)w2)[lane];
    for (int l = warp; l < SL; l += 4) {
        float4 zv = ((const float4*)(z + (size_t)(b * SL + l) * D))[lane];
        float x0 = 1.0f / (1.0f + __expf(-(zv.x + hv.x)));
        float x1 = 1.0f / (1.0f + __expf(-(zv.y + hv.y)));
        float x2 = 1.0f / (1.0f + __expf(-(zv.z + hv.z)));
        float x3 = 1.0f / (1.0f + __expf(-(zv.w + hv.w)));
        float s = x0 * wv.x + x1 * wv.y + x2 * wv.z + x3 * wv.w;
#pragma unroll
        for (int off = 16; off > 0; off >>= 1) s += __shfl_xor_sync(0xffffffffu, s, off);
        if (lane == 0) sb[l] = s;
    }
    __syncthreads();
    const float* sp = seqh + (size_t)b * SL * D + t;
    float a = 0.f;
#pragma unroll 4
    for (int l = 0; l < SL; l++) a += sb[l] * sp[(size_t)l * D];
    out[(size_t)b * D + t] = a + acc[(size_t)uidx[b] * D + t] * (1.0f / 3.0f);
}

// ============================================================================
extern "C" void kernel_launch(void* const* d_in, const int* in_sizes, int n_in,
                              void* d_out, int out_size) {
    const float* nodes_emb   = (const float*)d_in[0];
    const float* pos_local   = (const float*)d_in[1];
    const float* fc_geo_w    = (const float*)d_in[2];
    const float* fc_geo_b    = (const float*)d_in[3];
    const float* in_proj_w   = (const float*)d_in[4];
    const float* in_proj_b   = (const float*)d_in[5];
    const float* out_proj_w  = (const float*)d_in[6];
    const float* out_proj_b  = (const float*)d_in[7];
    const float* pos_glob    = (const float*)d_in[8];
    const float* w1_w        = (const float*)d_in[9];
    const float* w1_b        = (const float*)d_in[10];
    const float* w_2         = (const float*)d_in[11];
    const float* glu1_w      = (const float*)d_in[12];
    const float* glu1_b      = (const float*)d_in[13];
    const float* glu2_w      = (const float*)d_in[14];
    const int*   G_rows      = (const int*)d_in[15];
    const int*   G_cols      = (const int*)d_in[16];
    const float* G_vals      = (const float*)d_in[17];
    const int*   HG_rows     = (const int*)d_in[18];
    const int*   HG_cols     = (const int*)d_in[19];
    const float* HG_vals     = (const float*)d_in[20];
    const int*   seqs        = (const int*)d_in[21];
    const int*   masks       = (const int*)d_in[22];
    const float* adjs        = (const float*)d_in[23];
    const int*   uidx        = (const int*)d_in[24];
    const float* lens        = (const float*)d_in[25];
    const int*   revs        = (const int*)d_in[26];
    float* out = (float*)d_out;

    float *nodesA, *acc, *nodesB, *gx, *gacc, *gt, *seq, *t1, *t2, *qkv, *o, *users, *hs;
    int *Gptr, *Gcur, *Gcol, *Hptr, *Hcur, *Hcol;
    float *Gval, *Hval;
    void* p;
    cudaGetSymbolAddress(&p, g_nodes); nodesA = (float*)p;
    cudaGetSymbolAddress(&p, g_acc);   acc    = (float*)p;
    cudaGetSymbolAddress(&p, g_tmp);   nodesB = (float*)p;
    cudaGetSymbolAddress(&p, g_gx);    gx     = (float*)p;
    cudaGetSymbolAddress(&p, g_gacc);  gacc   = (float*)p;
    cudaGetSymbolAddress(&p, g_gt);    gt     = (float*)p;
    cudaGetSymbolAddress(&p, g_seq);   seq    = (float*)p;
    cudaGetSymbolAddress(&p, g_t1);    t1     = (float*)p;
    cudaGetSymbolAddress(&p, g_t2);    t2     = (float*)p;
    cudaGetSymbolAddress(&p, g_qkv);   qkv    = (float*)p;
    cudaGetSymbolAddress(&p, g_o);     o      = (float*)p;
    cudaGetSymbolAddress(&p, g_users); users  = (float*)p;
    cudaGetSymbolAddress(&p, g_hs);    hs     = (float*)p;
    cudaGetSymbolAddress(&p, g_Gptr);  Gptr   = (int*)p;
    cudaGetSymbolAddress(&p, g_Gcur);  Gcur   = (int*)p;
    cudaGetSymbolAddress(&p, g_Gcol);  Gcol   = (int*)p;
    cudaGetSymbolAddress(&p, g_Gval);  Gval   = (float*)p;
    cudaGetSymbolAddress(&p, g_Hptr);  Hptr   = (int*)p;
    cudaGetSymbolAddress(&p, g_Hcur);  Hcur   = (int*)p;
    cudaGetSymbolAddress(&p, g_Hcol);  Hcol   = (int*)p;
    cudaGetSymbolAddress(&p, g_Hval);  Hval   = (float*)p;

    const int GEMM_SM = 2 * 128 * 36 * 4;                   // 36864
    cudaFuncSetAttribute((const void*)k_geo_mma,  cudaFuncAttributeMaxDynamicSharedMemorySize, GEOMMA_SM);
    cudaFuncSetAttribute((const void*)k_attn_mma, cudaFuncAttributeMaxDynamicSharedMemorySize, ATTN2_SM);
    cudaFuncSetAttribute((const void*)k_gemm<0>,  cudaFuncAttributeMaxDynamicSharedMemorySize, GEMM_SM);
    cudaFuncSetAttribute((const void*)k_gemm<3>,  cudaFuncAttributeMaxDynamicSharedMemorySize, GEMM_SM);
    cudaFuncSetAttribute((const void*)k_gemm<4>,  cudaFuncAttributeMaxDynamicSharedMemorySize, GEMM_SM);

    const int M128 = MROWS / 128;          // 800
    const float* nullf = (const float*)0;
    const int*   nulli = (const int*)0;

    // persistent streams/events (created once on the correctness call so their
    // lazy device allocations land inside the pre-capture baseline)
    static cudaStream_t sA = 0, sB = 0;
    static cudaEvent_t evFork = 0, evG = 0, evH = 0;
    if (sA == 0) {
        cudaStreamCreateWithFlags(&sA, cudaStreamNonBlocking);
        cudaStreamCreateWithFlags(&sB, cudaStreamNonBlocking);
        cudaEventCreateWithFlags(&evFork, cudaEventDisableTiming);
        cudaEventCreateWithFlags(&evG,    cudaEventDisableTiming);
        cudaEventCreateWithFlags(&evH,    cudaEventDisableTiming);
    }

    cudaEventRecord(evFork, 0);
    cudaStreamWaitEvent(sA, evFork, 0);
    cudaStreamWaitEvent(sB, evFork, 0);

    // ---- stream A: CSR-G build ----
    cudaMemsetAsync(Gcur, 0, (NGROWS + 1) * sizeof(int), sA);
    k_hist<<<(NNZG + 255) / 256, 256, 0, sA>>>(G_rows, Gcur, NNZG);
    k_scan<<<1, 1024, 0, sA>>>(Gcur, Gptr, NGROWS);
    k_scat<<<(NNZG + 255) / 256, 256, 0, sA>>>(G_rows, G_cols, G_vals, Gcur, Gcol, Gval, NNZG);
    cudaEventRecord(evG, sA);

    // ---- stream B: full hypergraph chain ----
    cudaMemcpyAsync(gx,   nodes_emb + (size_t)NU * D, (size_t)NP * D * 4, cudaMemcpyDeviceToDevice, sB);
    cudaMemcpyAsync(gacc, nodes_emb + (size_t)NU * D, (size_t)NP * D * 4, cudaMemcpyDeviceToDevice, sB);
    cudaMemsetAsync(Hcur, 0, (NP + 1) * sizeof(int), sB);
    k_hist<<<(NNZH + 255) / 256, 256, 0, sB>>>(HG_rows, Hcur, NNZH);
    k_scan<<<1, 1024, 0, sB>>>(Hcur, Hptr, NP);
    k_scat<<<(NNZH + 255) / 256, 256, 0, sB>>>(HG_rows, HG_cols, HG_vals, Hcur, Hcol, Hval, NNZH);
    k_spmm_csr<<<(NP + 7) / 8, 256, 0, sB>>>(Hptr, Hcol, Hval, gx, gt, gacc, NP);
    k_spmm_csr<<<(NP + 7) / 8, 256, 0, sB>>>(Hptr, Hcol, Hval, gt, gx, gacc, NP);
    cudaEventRecord(evH, sB);

    // ---- main stream: init + local layers ----
    cudaMemcpyAsync(nodesA, nodes_emb, (size_t)NN * D * 4, cudaMemcpyDeviceToDevice, 0);
    cudaMemcpyAsync(acc,    nodes_emb, (size_t)NN * D * 4, cudaMemcpyDeviceToDevice, 0);

    float* cur = nodesA;
    float* nxt = nodesB;
    for (int layer = 0; layer < 2; ++layer) {
        k_geo_mma<<<BB, 512, GEOMMA_SM>>>(adjs, seqs, cur, seq, t1);
        k_gemm<3><<<dim3(M128, 1), 256, GEMM_SM>>>(t1, fc_geo_w, fc_geo_b, t1, MROWS, 128, 128, seq, pos_local, nulli);
        k_gemm<0><<<dim3(M128, 3), 256, GEMM_SM>>>(t1, in_proj_w, in_proj_b, qkv, MROWS, 384, 128, nullf, nullf, nulli);
        k_attn_mma<<<BB * NHD, 512, ATTN2_SM>>>(qkv, o);
        // users = umean @ out_proj^T + bias (mean commutes with linear proj)
        k_gemm<0><<<dim3(BB / 128, 1), 256, GEMM_SM>>>(o, out_proj_w, out_proj_b, users, BB, 128, 128, nullf, nullf, nulli);
        k_scatteru<<<BB, 128>>>(users, uidx, cur);
        if (layer == 0) cudaStreamWaitEvent(0, evG, 0);
        k_spmm_csr<<<(NGROWS + 7) / 8, 256>>>(Gptr, Gcol, Gval, cur, nxt, acc, NGROWS);
        float* sw = cur; cur = nxt; nxt = sw;
    }

    // ---- join hypergraph chain, outputs ----
    cudaStreamWaitEvent(0, evH, 0);
    k_pois<<<(NP * D / 4 + 255) / 256, 256>>>(acc, gacc, out);

    // ---- final gated readout (concat fused into w1 gemm, ACT=4) ----
    k_fushs<<<BB, 128>>>(revs, acc, gacc, lens, seq, hs);
    k_gemm<4><<<dim3(M128, 1), 256, GEMM_SM>>>(seq, w1_w, w1_b, t1, MROWS, 128, 256, pos_glob, nullf, masks);
    k_gemm<0><<<dim3(M128, 1), 256, GEMM_SM>>>(t1, glu1_w, glu1_b, t2, MROWS, 128, 128, nullf, nullf, nulli);
    k_gemm<0><<<dim3(BB / 128, 1), 256, GEMM_SM>>>(hs, glu2_w, nullf, users, BB, 128, 128, nullf, nullf, nulli);
    k_gate<<<BB, 128>>>(t2, users, w_2, seq, acc, uidx, out);
}